// round 17
// baseline (speedup 1.0000x reference)
#include <cuda_runtime.h>
#include <math.h>
#include <stdint.h>

#define BSZ   4
#define NSEQ  4096
#define DIM   1024
#define TOPK  8
#define NCAND 16
#define MROWS (BSZ * NSEQ)
#define KS8   (DIM / 8)
#define NSB   272
#define WSZF  ((size_t)DIM * DIM)

typedef unsigned long long ULL;

// ---------------- scratch (__device__ globals; no allocation allowed) -------
__device__ __align__(128) float g_u[(size_t)MROWS * DIM];     // prep partials, then U
__device__ __align__(128) float g_traw[(size_t)MROWS * DIM];  // raw T (rescore)
__device__ float g_pval[(size_t)BSZ * NSB * 256 * TOPK];
__device__ int   g_pidx[(size_t)BSZ * NSB * 256 * TOPK];
__device__ float g_bvo[DIM];
__device__ float g_y[DIM];
__device__ float g_w[MROWS];
__device__ __align__(128) float g_ahi[(size_t)MROWS * DIM];
__device__ __align__(128) float g_alo[(size_t)MROWS * DIM];
__device__ __align__(128) float g_qhi[(size_t)MROWS * DIM];   // A-fmt Thi
__device__ __align__(128) float g_khi[(size_t)MROWS * DIM];   // B-fmt (Wo/Wk then S hi)
__device__ __align__(128) float g_klo[(size_t)MROWS * DIM];   // B-fmt lo (prep only)
__device__ __align__(128) float g_wthi[2][WSZF];              // slot0 G, slot1 Wvo
__device__ __align__(128) float g_wtlo[2][WSZF];

// ---------------- helpers -----------------------------------------------------
__device__ __forceinline__ uint32_t smem_u32(const void* p) {
    uint32_t a;
    asm("{ .reg .u64 t; cvta.to.shared.u64 t, %1; cvt.u32.u64 %0, t; }"
        : "=r"(a) : "l"(p));
    return a;
}
__device__ __forceinline__ float tf32r(float x) {
    uint32_t u;
    asm("cvt.rna.tf32.f32 %0, %1;" : "=r"(u) : "f"(x));
    return __uint_as_float(u);
}
__device__ __forceinline__ void cpasync16(uint32_t saddr, const void* g) {
    asm volatile("cp.async.cg.shared.global [%0], [%1], 16;"
                 :: "r"(saddr), "l"(g));
}
#define CP_COMMIT() asm volatile("cp.async.commit_group;" ::: "memory")
#define CP_WAIT_1() asm volatile("cp.async.wait_group 1;" ::: "memory")
#define CP_WAIT_0() asm volatile("cp.async.wait_group 0;" ::: "memory")

__device__ __forceinline__ void mma8(float4& c, const uint4& a, const uint2& b) {
    asm volatile(
        "mma.sync.aligned.m16n8k8.row.col.f32.tf32.tf32.f32 "
        "{%0,%1,%2,%3}, {%4,%5,%6,%7}, {%8,%9}, {%0,%1,%2,%3};"
        : "+f"(c.x), "+f"(c.y), "+f"(c.z), "+f"(c.w)
        : "r"(a.x), "r"(a.y), "r"(a.z), "r"(a.w), "r"(b.x), "r"(b.y));
}

// ---------------- split+pack A-format: X[M,K] row-major ---------------------
__global__ __launch_bounds__(256) void split_pack_a(
    const float* __restrict__ X, float4* __restrict__ Phi, float4* __restrict__ Plo) {
    const int atom = blockIdx.x * 8 + (threadIdx.x >> 5);
    const int lane = threadIdx.x & 31;
    const int mt = atom >> 7;
    const int ks = atom & 127;
    const int g = lane >> 2, t = lane & 3;
    const size_t r0 = (size_t)(mt * 16 + g) * DIM + ks * 8 + t;
    const size_t r1 = r0 + 8 * DIM;
    float x0 = X[r0], x1 = X[r1], x2 = X[r0 + 4], x3 = X[r1 + 4];
    float4 h, l;
    h.x = tf32r(x0); l.x = tf32r(x0 - h.x);
    h.y = tf32r(x1); l.y = tf32r(x1 - h.y);
    h.z = tf32r(x2); l.z = tf32r(x2 - h.z);
    h.w = tf32r(x3); l.w = tf32r(x3 - h.w);
    Phi[(size_t)atom * 32 + lane] = h;
    Plo[(size_t)atom * 32 + lane] = l;
}

// ---------------- split+pack W (B-format) ------------------------------------
__global__ __launch_bounds__(256) void split_pack_w(
    const float* __restrict__ W, float2* __restrict__ Phi, float2* __restrict__ Plo) {
    const int atom = blockIdx.x * 8 + (threadIdx.x >> 5);
    const int lane = threadIdx.x & 31;
    const int nt = atom >> 7;
    const int ks = atom & 127;
    const int g = lane >> 2, t = lane & 3;
    float x0 = W[(size_t)(ks * 8 + t) * DIM + nt * 8 + g];
    float x1 = W[(size_t)(ks * 8 + t + 4) * DIM + nt * 8 + g];
    float2 h, l;
    h.x = tf32r(x0); l.x = tf32r(x0 - h.x);
    h.y = tf32r(x1); l.y = tf32r(x1 - h.y);
    Phi[(size_t)atom * 32 + lane] = h;
    Plo[(size_t)atom * 32 + lane] = l;
}

// ---------------- split+pack row-major [N,K] -> B-format ---------------------
__global__ __launch_bounds__(256) void split_pack_kb(
    const float* __restrict__ X, float2* __restrict__ Phi, float2* __restrict__ Plo) {
    const int atom = blockIdx.x * 8 + (threadIdx.x >> 5);
    const int lane = threadIdx.x & 31;
    const int nt = atom >> 7;
    const int ks = atom & 127;
    const int g = lane >> 2, t = lane & 3;
    const size_t base = (size_t)(nt * 8 + g) * DIM + ks * 8 + t;
    float x0 = X[base];
    float x1 = X[base + 4];
    float2 h, l;
    h.x = tf32r(x0); l.x = tf32r(x0 - h.x);
    h.y = tf32r(x1); l.y = tf32r(x1 - h.y);
    Phi[(size_t)atom * 32 + lane] = h;
    Plo[(size_t)atom * 32 + lane] = l;
}

// ------- fused S pack: A-format hi/lo + B-format hi (B lo unused) ------------
__global__ __launch_bounds__(256) void split_pack_s(
    const float* __restrict__ X,
    float4* __restrict__ Ahi, float4* __restrict__ Alo,
    float2* __restrict__ Bhi) {
    const int atom = blockIdx.x * 8 + (threadIdx.x >> 5);
    const int lane = threadIdx.x & 31;
    const int mt = atom >> 7;
    const int ks = atom & 127;
    const int g = lane >> 2, t = lane & 3;
    const size_t r0 = (size_t)(mt * 16 + g) * DIM + ks * 8 + t;
    const size_t r1 = r0 + 8 * DIM;
    float x0 = X[r0], x1 = X[r1], x2 = X[r0 + 4], x3 = X[r1 + 4];
    float4 h, l;
    h.x = tf32r(x0); l.x = tf32r(x0 - h.x);
    h.y = tf32r(x1); l.y = tf32r(x1 - h.y);
    h.z = tf32r(x2); l.z = tf32r(x2 - h.z);
    h.w = tf32r(x3); l.w = tf32r(x3 - h.w);
    Ahi[(size_t)atom * 32 + lane] = h;
    Alo[(size_t)atom * 32 + lane] = l;
    const size_t b0 = ((size_t)(2 * mt) * KS8 + ks) * 32 + lane;
    const size_t b1 = b0 + (size_t)KS8 * 32;
    Bhi[b0] = make_float2(h.x, h.z);
    Bhi[b1] = make_float2(h.y, h.w);
}

// ---------------- bvo = bv @ Wo + bo ----------------------------------------
__global__ __launch_bounds__(128) void bvo_kernel(
    const float* __restrict__ bv, const float* __restrict__ Wo,
    const float* __restrict__ bo, float* __restrict__ bvo) {
    const int n = blockIdx.x * 128 + threadIdx.x;
    float acc = bo[n];
    for (int k = 0; k < DIM; k++) acc += bv[k] * Wo[(size_t)k * DIM + n];
    bvo[n] = acc;
}

// ---------------- y[d] = Wk[d,:] . bq ----------------------------------------
__global__ __launch_bounds__(256) void ydot_kernel(
    const float* __restrict__ Wk, const float* __restrict__ bq,
    float* __restrict__ y) {
    const int wid = threadIdx.x >> 5, lane = threadIdx.x & 31;
    const int row = blockIdx.x * 8 + wid;
    const float4* r4 = (const float4*)(Wk + (size_t)row * DIM);
    const float4* b4 = (const float4*)bq;
    float acc = 0.f;
    for (int i = lane; i < DIM / 4; i += 32) {
        float4 a = r4[i], b = b4[i];
        acc += a.x * b.x + a.y * b.y + a.z * b.z + a.w * b.w;
    }
#pragma unroll
    for (int o = 16; o; o >>= 1) acc += __shfl_xor_sync(0xffffffffu, acc, o);
    if (lane == 0) y[row] = acc;
}

// ---------------- w[m] = (S[m,:] . y) / 32 -----------------------------------
__global__ __launch_bounds__(256) void wdot_kernel(
    const float* __restrict__ S, const float* __restrict__ y,
    float* __restrict__ w) {
    const int wid = threadIdx.x >> 5, lane = threadIdx.x & 31;
    const int row = blockIdx.x * 8 + wid;
    const float4* r4 = (const float4*)(S + (size_t)row * DIM);
    const float4* y4 = (const float4*)y;
    float acc = 0.f;
    for (int i = lane; i < DIM / 4; i += 32) {
        float4 a = r4[i], b = y4[i];
        acc += a.x * b.x + a.y * b.y + a.z * b.z + a.w * b.w;
    }
#pragma unroll
    for (int o = 16; o; o >>= 1) acc += __shfl_xor_sync(0xffffffffu, acc, o);
    if (lane == 0) w[row] = acc * 0.03125f;
}

// ---------- shared TF32 mainloop (256x128 tile, BK=16), MODE in {1,2,3} -----
#define GEMM_SMEM (3 * 12288 * 4)

template <int MODE>
__device__ __forceinline__ void mma_mainloop(
    float* sm, const float* __restrict__ Ahi, const float* __restrict__ Alo,
    const float* __restrict__ Bhi, const float* __restrict__ Blo,
    int br16, int bn16, int kc0, int iters, float4 (&acc)[4][8]) {
    const int tid = threadIdx.x;
    const int lane = tid & 31, wid = tid >> 5;
    const int wy = wid >> 1, wx = wid & 1;
    const uint32_t smb = smem_u32(sm);

    auto load_stage = [&](int kc, int s) {
        const uint32_t sb = smb + s * 49152;
#pragma unroll
        for (int j = 0; j < 4; j++) {
            const int cA = tid + j * 256;
            const int mtl = cA >> 6, off = cA & 63;
            const uint32_t so = sb + (uint32_t)(mtl * 256 + off * 4) * 4;
            const size_t go = ((size_t)(br16 + mtl) * KS8 + kc * 2) * 128 + off * 4;
            cpasync16(so, Ahi + go);
            if (MODE >= 2) cpasync16(so + 4096 * 4, Alo + go);
        }
#pragma unroll
        for (int j = 0; j < 2; j++) {
            const int cB = tid + j * 256;
            const int ntl = cB >> 5, off = cB & 31;
            const uint32_t so = sb + (uint32_t)(8192 + ntl * 128 + off * 4) * 4;
            const size_t go = ((size_t)(bn16 + ntl) * KS8 + kc * 2) * 64 + off * 4;
            cpasync16(so, Bhi + go);
            if (MODE >= 3) cpasync16(so + 2048 * 4, Blo + go);
        }
    };

    load_stage(kc0, 0); CP_COMMIT();
    load_stage(kc0 + 1, 1); CP_COMMIT();

#pragma unroll
    for (int i = 0; i < 4; i++)
#pragma unroll
        for (int j = 0; j < 8; j++) acc[i][j] = make_float4(0.f, 0.f, 0.f, 0.f);

    for (int c = 0; c < iters; c++) {
        if (c < iters - 2) { CP_WAIT_1(); } else { CP_WAIT_0(); }
        __syncthreads();
        if (c + 2 < iters) { load_stage(kc0 + c + 2, (c + 2) % 3); CP_COMMIT(); }
        const float* st = sm + (c % 3) * 12288;
#pragma unroll
        for (int ks = 0; ks < 2; ks++) {
            uint4 Ah[4], Al[4];
            uint2 Bh[8], Bl[8];
#pragma unroll
            for (int i = 0; i < 4; i++) {
                const float* p = st + ((wy * 4 + i) * 2 + ks) * 128 + lane * 4;
                Ah[i] = *(const uint4*)p;
                if (MODE >= 2) Al[i] = *(const uint4*)(p + 4096);
            }
#pragma unroll
            for (int j = 0; j < 8; j++) {
                const float* p = st + 8192 + ((wx * 8 + j) * 2 + ks) * 64 + lane * 2;
                Bh[j] = *(const uint2*)p;
                if (MODE >= 3) Bl[j] = *(const uint2*)(p + 2048);
            }
#pragma unroll
            for (int i = 0; i < 4; i++)
#pragma unroll
                for (int j = 0; j < 8; j++) {
                    mma8(acc[i][j], Ah[i], Bh[j]);
                    if (MODE >= 3) mma8(acc[i][j], Ah[i], Bl[j]);
                    if (MODE >= 2) mma8(acc[i][j], Al[i], Bh[j]);
                }
        }
    }
}

// --------- fused prep GEMMs: Wvo = Wv@Wo and G = Wq@Wk^T, split-K x2 --------
__global__ __launch_bounds__(256, 1) void gemm_prep_kernel(
    const float* __restrict__ Ahi, const float* __restrict__ Alo,
    const float* __restrict__ Bhi, const float* __restrict__ Blo,
    float* __restrict__ P) {
    extern __shared__ float sm[];
    const int wsel = blockIdx.z >> 1;
    const int khalf = blockIdx.z & 1;
    const int tid = threadIdx.x;
    const int lane = tid & 31, wid = tid >> 5;
    const int wy = wid >> 1, wx = wid & 1;
    const int g = lane >> 2, t = lane & 3;
    const int m0 = blockIdx.y * 256, n0 = blockIdx.x * 128;

    float4 acc[4][8];
    mma_mainloop<3>(sm, Ahi, Alo, Bhi, Blo,
                    wsel * 64 + blockIdx.y * 16, wsel * 128 + blockIdx.x * 16,
                    khalf * 32, 32, acc);

    float* out = P + (size_t)(wsel * 2 + khalf) * DIM * DIM;
#pragma unroll
    for (int i = 0; i < 4; i++) {
        const int r0 = m0 + wy * 64 + i * 16 + g;
#pragma unroll
        for (int j = 0; j < 8; j++) {
            const int col = n0 + wx * 64 + j * 8 + t * 2;
            *(float2*)(out + (size_t)r0 * DIM + col) =
                make_float2(acc[i][j].x, acc[i][j].y);
            *(float2*)(out + (size_t)(r0 + 8) * DIM + col) =
                make_float2(acc[i][j].z, acc[i][j].w);
        }
    }
}

// --------- sum split-K partials + pack B-format into weight slots ------------
__global__ __launch_bounds__(256) void prep_pack_sum(
    const float* __restrict__ P, float2* __restrict__ WHi, float2* __restrict__ WLo) {
    const int bx = blockIdx.x;
    const int w = bx >> 11;
    const float* p0 = P + (size_t)(w == 0 ? 2 : 0) * DIM * DIM;
    const float* p1 = p0 + (size_t)DIM * DIM;
    float2* dhi = WHi + (size_t)w * WSZF / 2;
    float2* dlo = WLo + (size_t)w * WSZF / 2;
    const int atom = (bx & 2047) * 8 + (threadIdx.x >> 5);
    const int lane = threadIdx.x & 31;
    const int nt = atom >> 7;
    const int ks = atom & 127;
    const int g = lane >> 2, t = lane & 3;
    const size_t i0 = (size_t)(ks * 8 + t) * DIM + nt * 8 + g;
    const size_t i1 = (size_t)(ks * 8 + t + 4) * DIM + nt * 8 + g;
    float x0 = p0[i0] + p1[i0];
    float x1 = p0[i1] + p1[i1];
    float2 h, l;
    h.x = tf32r(x0); l.x = tf32r(x0 - h.x);
    h.y = tf32r(x1); l.y = tf32r(x1 - h.y);
    dhi[(size_t)atom * 32 + lane] = h;
    dlo[(size_t)atom * 32 + lane] = l;
}

// T-only projection: T = S@G (3x), writes Thi packed + raw. grid (8, 64).
__global__ __launch_bounds__(256, 1) void gemm_t_kernel(
    const float* __restrict__ Ahi, const float* __restrict__ Alo,
    const float* __restrict__ Whi, const float* __restrict__ Wlo,
    float* __restrict__ Thi, float* __restrict__ Traw) {
    extern __shared__ float sm[];
    const int nxt = blockIdx.x;
    const int tid = threadIdx.x;
    const int lane = tid & 31, wid = tid >> 5;
    const int wy = wid >> 1, wx = wid & 1;
    const int g = lane >> 2, t = lane & 3;
    const int m0 = blockIdx.y * 256, n0 = nxt * 128;

    float4 acc[4][8];
    mma_mainloop<3>(sm, Ahi, Alo, Whi, Wlo,
                    blockIdx.y * 16, nxt * 16, 0, 64, acc);

    // raw T write (for exact rescore)
#pragma unroll
    for (int i = 0; i < 4; i++) {
        const int r0 = m0 + wy * 64 + i * 16 + g;
#pragma unroll
        for (int j = 0; j < 8; j++) {
            const int col = n0 + wx * 64 + j * 8 + t * 2;
            *(float2*)(Traw + (size_t)r0 * DIM + col) =
                make_float2(acc[i][j].x, acc[i][j].y);
            *(float2*)(Traw + (size_t)(r0 + 8) * DIM + col) =
                make_float2(acc[i][j].z, acc[i][j].w);
        }
    }

    __syncthreads();  // pipeline smem free
#pragma unroll
    for (int i = 0; i < 4; i++) {
        const int r0 = wy * 64 + i * 16 + g;
#pragma unroll
        for (int j = 0; j < 8; j++) {
            const int col = wx * 64 + j * 8 + t * 2;
            *(float2*)&sm[r0 * 132 + col] = make_float2(acc[i][j].x, acc[i][j].y);
            *(float2*)&sm[(r0 + 8) * 132 + col] = make_float2(acc[i][j].z, acc[i][j].w);
        }
    }
    __syncthreads();

    // pack Thi (A-format hi only; scores pass is 1x)
    for (int a = wid; a < 256; a += 8) {
        const int amt = a >> 4, aks = a & 15;
        const float* bp = sm + (amt * 16 + g) * 132 + aks * 8 + t;
        float4 h;
        h.x = tf32r(bp[0]);
        h.y = tf32r(bp[8 * 132]);
        h.z = tf32r(bp[4]);
        h.w = tf32r(bp[8 * 132 + 4]);
        const size_t atom = (size_t)(blockIdx.y * 16 + amt) * KS8 + (nxt * 16 + aks);
        ((float4*)Thi)[atom * 32 + lane] = h;
    }
}

// ------- fused U + scores kernel: 1600 equal mode-1 blocks -------------------
// bx < 512: U = S@Wvo (1x, raw). bx >= 512: supertile 1x scores + candidates.
#define SSC_SMEM ((3 * 12288 + 128 * 72 + 256 * 8 + 256 * 8 + 128) * 4)

__global__ __launch_bounds__(256, 1) void fused_us_kernel(
    const float* __restrict__ Ahi,   // S A-fmt hi
    const float* __restrict__ WvoHi, // Wvo B-fmt hi (slot 1)
    const float* __restrict__ Thi,   // T A-fmt hi
    const float* __restrict__ Shi,   // S B-fmt hi
    const float* __restrict__ w,
    float* __restrict__ U,
    float* __restrict__ pval, int* __restrict__ pidx) {
    extern __shared__ float sm[];
    const int tid = threadIdx.x;
    const int lane = tid & 31, wid = tid >> 5;
    const int wy = wid >> 1, wx = wid & 1;
    const int g = lane >> 2, t = lane & 3;

    if (blockIdx.x < 512) {
        // ---- U branch ----
        const int nxt = blockIdx.x & 7;
        const int my = blockIdx.x >> 3;   // 0..63
        const int m0 = my * 256, n0 = nxt * 128;
        float4 acc[4][8];
        mma_mainloop<1>(sm, Ahi, (const float*)0, WvoHi, (const float*)0,
                        my * 16, nxt * 16, 0, 64, acc);
#pragma unroll
        for (int i = 0; i < 4; i++) {
            const int r0 = m0 + wy * 64 + i * 16 + g;
#pragma unroll
            for (int j = 0; j < 8; j++) {
                const int col = n0 + wx * 64 + j * 8 + t * 2;
                *(float2*)(U + (size_t)r0 * DIM + col) =
                    make_float2(acc[i][j].x, acc[i][j].y);
                *(float2*)(U + (size_t)(r0 + 8) * DIM + col) =
                    make_float2(acc[i][j].z, acc[i][j].w);
            }
        }
        return;
    }

    // ---- scores branch ----
    float* sc = sm + 36864;
    float* tval = sm + 46080;
    int* tidx = (int*)(sm + 48128);
    float* wsc = sm + 50176;

    const int sidx = blockIdx.x - 512;
    const int b = sidx / NSB;
    const int bidx = sidx - b * NSB;

    int sq = (int)((sqrtf(4.0f * (float)bidx + 1.0f) - 1.0f) * 0.5f);
    while ((sq + 1) * (sq + 2) <= bidx) sq++;
    while (sq * (sq + 1) > bidx) sq--;
    const int kt = bidx - sq * (sq + 1);
    const int q0 = sq * 256, k0 = kt * 128;

    for (int i = tid; i < 256 * TOPK; i += 256) {
        tval[i] = -INFINITY;
        tidx[i] = 0;
    }
    if (tid < 128) wsc[tid] = w[b * NSEQ + k0 + tid];

    float4 acc[4][8];
    mma_mainloop<1>(sm, Thi, (const float*)0, Shi, (const float*)0,
                    b * 256 + sq * 16, b * 512 + kt * 16, 0, 64, acc);

#pragma unroll
    for (int rh = 0; rh < 2; rh++) {
#pragma unroll
        for (int h = 0; h < 2; h++) {
            if ((wy >> 1) == rh && wx == h) {
#pragma unroll
                for (int i = 0; i < 4; i++) {
                    const int rl = wy * 64 + i * 16 + g;
                    const int srow = rl - rh * 128;
#pragma unroll
                    for (int j = 0; j < 8; j++) {
                        const int col = j * 8 + t * 2;
                        const int lc = h * 64 + col;
                        const int gc = k0 + lc;
                        const int gr0 = q0 + rl, gr1 = gr0 + 8;
                        const float w0 = wsc[lc], w1 = wsc[lc + 1];
                        float v0 = acc[i][j].x * 0.03125f + w0;
                        float v1 = acc[i][j].y * 0.03125f + w1;
                        float v2 = acc[i][j].z * 0.03125f + w0;
                        float v3 = acc[i][j].w * 0.03125f + w1;
                        if (gc + 0 > gr0) v0 = -INFINITY;
                        if (gc + 1 > gr0) v1 = -INFINITY;
                        if (gc + 0 > gr1) v2 = -INFINITY;
                        if (gc + 1 > gr1) v3 = -INFINITY;
                        *(float2*)&sc[srow * 72 + col] = make_float2(v0, v1);
                        *(float2*)&sc[(srow + 8) * 72 + col] = make_float2(v2, v3);
                    }
                }
            }
            __syncthreads();
            if (tid < 128) {
                const int row = rh * 128 + tid;
                float tv[TOPK]; int ti[TOPK];
#pragma unroll
                for (int j = 0; j < TOPK; j++) { tv[j] = tval[row * 8 + j]; ti[j] = tidx[row * 8 + j]; }
                float vmin = tv[0]; int mpos = 0;
#pragma unroll
                for (int j = 1; j < TOPK; j++) if (tv[j] < vmin) { vmin = tv[j]; mpos = j; }
                const int cbase = k0 + h * 64;
                for (int cc = 0; cc < 64; cc++) {
                    const float vv = sc[tid * 72 + cc];
                    if (vv > vmin) {
                        tv[mpos] = vv; ti[mpos] = cbase + cc;
                        vmin = tv[0]; mpos = 0;
#pragma unroll
                        for (int j = 1; j < TOPK; j++) if (tv[j] < vmin) { vmin = tv[j]; mpos = j; }
                    }
                }
#pragma unroll
                for (int j = 0; j < TOPK; j++) { tval[row * 8 + j] = tv[j]; tidx[row * 8 + j] = ti[j]; }
            }
            __syncthreads();
        }
    }

    const size_t base = (((size_t)b * NSB + bidx) * 256 + tid) * TOPK;
#pragma unroll
    for (int j = 0; j < TOPK; j++) {
        pval[base + j] = tval[tid * 8 + j];
        pidx[base + j] = tidx[tid * 8 + j];
    }
}

// ------- merge top-16 (1x) -> exact rescore -> top-8 softmax -> gather -------
__global__ __launch_bounds__(128) void merge_rescore_gather(
    const float* __restrict__ pv, const int* __restrict__ pi,
    const float* __restrict__ Traw, const float* __restrict__ S,
    const float* __restrict__ w, const float* __restrict__ U,
    const float* __restrict__ bvo, float* __restrict__ out) {
    const int row = blockIdx.x;
    const int b = row >> 12, rr = row & 4095;
    const int qt = rr >> 7;
    const int sq = qt >> 1;
    const int rib = rr - sq * 256;
    const size_t sbase = ((size_t)b * NSB + (size_t)sq * (sq + 1)) * 256 + rib;

    __shared__ float trow[DIM];
    __shared__ float cval[NCAND];
    __shared__ int   cidx[NCAND];
    __shared__ float cex[NCAND];
    __shared__ float ps[TOPK];
    __shared__ int   ids[TOPK];

    const int tid = threadIdx.x;
    const int lane = tid & 31, wid = tid >> 5;

    {
        const float4* tr = (const float4*)(Traw + (size_t)row * DIM);
        ((float4*)trow)[tid] = tr[tid];
        ((float4*)trow)[tid + 128] = tr[tid + 128];
    }

    if (tid < 32) {
        float v[TOPK]; int id8[TOPK];
        if (lane <= qt) {
            const size_t base = (sbase + (size_t)lane * 256) * TOPK;
#pragma unroll
            for (int j = 0; j < TOPK; j++) { v[j] = pv[base + j]; id8[j] = pi[base + j]; }
        } else {
#pragma unroll
            for (int j = 0; j < TOPK; j++) { v[j] = -INFINITY; id8[j] = 0; }
        }
#pragma unroll
        for (int r = 0; r < NCAND; r++) {
            float lm = v[0]; int ls = 0;
#pragma unroll
            for (int j = 1; j < TOPK; j++) if (v[j] > lm) { lm = v[j]; ls = j; }
            float m = lm; int who = lane;
#pragma unroll
            for (int o = 16; o; o >>= 1) {
                float om = __shfl_xor_sync(0xffffffffu, m, o);
                int ow = __shfl_xor_sync(0xffffffffu, who, o);
                if (om > m || (om == m && ow < who)) { m = om; who = ow; }
            }
            int widx = 0;
#pragma unroll
            for (int j = 0; j < TOPK; j++) if (j == ls) widx = id8[j];
            const int gidx = __shfl_sync(0xffffffffu, widx, who);
            if (lane == 0) { cval[r] = m; cidx[r] = gidx; }
            if (lane == who) {
#pragma unroll
                for (int j = 0; j < TOPK; j++) if (j == ls) v[j] = -INFINITY;
            }
        }
    }
    __syncthreads();

    for (int c = wid; c < NCAND; c += 4) {
        const float v1 = cval[c];
        const int idx = cidx[c];
        float acc = 0.f;
        if (v1 != -INFINITY) {
            const float4* srow = (const float4*)(S + ((size_t)b * NSEQ + idx) * DIM);
            const float4* tr4 = (const float4*)trow;
            for (int i = lane; i < DIM / 4; i += 32) {
                float4 s = srow[i], tt = tr4[i];
                acc += tt.x * s.x + tt.y * s.y + tt.z * s.z + tt.w * s.w;
            }
        }
#pragma unroll
        for (int o = 16; o; o >>= 1) acc += __shfl_xor_sync(0xffffffffu, acc, o);
        if (lane == 0)
            cex[c] = (v1 != -INFINITY)
                         ? acc * 0.03125f + w[b * NSEQ + idx]
                         : -INFINITY;
    }
    __syncthreads();

    if (tid == 0) {
        float ev[NCAND]; int ei[NCAND];
#pragma unroll
        for (int j = 0; j < NCAND; j++) { ev[j] = cex[j]; ei[j] = cidx[j]; }
        float tv[TOPK]; int ti[TOPK];
#pragma unroll
        for (int r = 0; r < TOPK; r++) {
            int m = 0; float best = ev[0];
#pragma unroll
            for (int j = 1; j < NCAND; j++) if (ev[j] > best) { best = ev[j]; m = j; }
            tv[r] = best; ti[r] = ei[m]; ev[m] = -INFINITY;
        }
        float mx = tv[0];
#pragma unroll
        for (int j = 1; j < TOPK; j++) mx = fmaxf(mx, tv[j]);
        float e[TOPK]; float ssum = 0.f;
#pragma unroll
        for (int j = 0; j < TOPK; j++) { e[j] = expf(tv[j] - mx); ssum += e[j]; }
        const float inv = 1.f / ssum;
#pragma unroll
        for (int j = 0; j < TOPK; j++) { ps[j] = e[j] * inv; ids[j] = ti[j]; }
    }
    __syncthreads();

    const float* ub = U + (size_t)b * NSEQ * DIM;
    const int c = tid * 8;
    float4 a0 = *(const float4*)(bvo + c);
    float4 a1 = *(const float4*)(bvo + c + 4);
#pragma unroll
    for (int j = 0; j < TOPK; j++) {
        const float4* vr = (const float4*)(ub + (size_t)ids[j] * DIM + c);
        const float pj = ps[j];
        float4 v0 = vr[0], v1 = vr[1];
        a0.x += pj * v0.x; a0.y += pj * v0.y; a0.z += pj * v0.z; a0.w += pj * v0.w;
        a1.x += pj * v1.x; a1.y += pj * v1.y; a1.z += pj * v1.z; a1.w += pj * v1.w;
    }
    float4* orow = (float4*)(out + (size_t)row * DIM + c);
    orow[0] = a0; orow[1] = a1;
}

// ---------------- launch -----------------------------------------------------
extern "C" void kernel_launch(void* const* d_in, const int* in_sizes, int n_in,
                              void* d_out, int out_size) {
    const float* S  = (const float*)d_in[0];
    const float* Wq = (const float*)d_in[1];
    const float* bq = (const float*)d_in[2];
    const float* Wk = (const float*)d_in[3];
    const float* bk = (const float*)d_in[4];  // row-const in softmax; drops out
    const float* Wv = (const float*)d_in[5];
    const float* bv = (const float*)d_in[6];
    const float* Wo = (const float*)d_in[7];
    const float* bo = (const float*)d_in[8];
    float* out = (float*)d_out;
    (void)bk;

    float *up, *trp, *pvp, *ahip, *alop;
    float *qhip, *khip, *klop, *wthip, *wtlop;
    float *bvop, *yp, *wp;
    int *pip;
    cudaGetSymbolAddress((void**)&up, g_u);
    cudaGetSymbolAddress((void**)&trp, g_traw);
    cudaGetSymbolAddress((void**)&pvp, g_pval);
    cudaGetSymbolAddress((void**)&pip, g_pidx);
    cudaGetSymbolAddress((void**)&ahip, g_ahi);
    cudaGetSymbolAddress((void**)&alop, g_alo);
    cudaGetSymbolAddress((void**)&qhip, g_qhi);
    cudaGetSymbolAddress((void**)&khip, g_khi);
    cudaGetSymbolAddress((void**)&klop, g_klo);
    cudaGetSymbolAddress((void**)&wthip, g_wthi);
    cudaGetSymbolAddress((void**)&wtlop, g_wtlo);
    cudaGetSymbolAddress((void**)&bvop, g_bvo);
    cudaGetSymbolAddress((void**)&yp, g_y);
    cudaGetSymbolAddress((void**)&wp, g_w);

    cudaFuncSetAttribute(gemm_prep_kernel,
                         cudaFuncAttributeMaxDynamicSharedMemorySize, GEMM_SMEM);
    cudaFuncSetAttribute(gemm_t_kernel,
                         cudaFuncAttributeMaxDynamicSharedMemorySize, GEMM_SMEM);
    cudaFuncSetAttribute(fused_us_kernel,
                         cudaFuncAttributeMaxDynamicSharedMemorySize, SSC_SMEM);

    const int WPACK_GRID = (DIM / 8) * KS8 / 8;   // 2048
    const int APACK_1K = (DIM / 16) * KS8 / 8;    // 1024

    // operand packs for prep: A buffer = [Wv | Wq], B buffer = [Wo | Wk]
    split_pack_a<<<APACK_1K, 256>>>(Wv, (float4*)ahip, (float4*)alop);
    split_pack_a<<<APACK_1K, 256>>>(Wq,
        (float4*)ahip + (size_t)8192 * 32, (float4*)alop + (size_t)8192 * 32);
    split_pack_w<<<WPACK_GRID, 256>>>(Wo, (float2*)khip, (float2*)klop);
    split_pack_kb<<<WPACK_GRID, 256>>>(Wk,
        (float2*)khip + (size_t)16384 * 32, (float2*)klop + (size_t)16384 * 32);

    // bias folds
    bvo_kernel<<<DIM / 128, 128>>>(bv, Wo, bo, bvop);
    ydot_kernel<<<DIM / 8, 256>>>(Wk, bq, yp);
    wdot_kernel<<<MROWS / 8, 256>>>(S, yp, wp);

    // fused prep GEMMs (split-K x2) + partial-sum pack
    gemm_prep_kernel<<<dim3(8, 4, 4), 256, GEMM_SMEM>>>(ahip, alop, khip, klop, up);
    prep_pack_sum<<<4096, 256>>>(up, (float2*)wthip, (float2*)wtlop);

    // fused S pack: A-fmt hi/lo + B-fmt hi
    split_pack_s<<<(MROWS / 16) * KS8 / 8, 256>>>(
        S, (float4*)ahip, (float4*)alop, (float2*)khip);

    // T = S@G (3x): homogeneous heavy wave
    gemm_t_kernel<<<dim3(8, MROWS / 256), 256, GEMM_SMEM>>>(
        ahip, alop, wthip, wtlop, qhip, trp);

    // fused U (1x) + scores (1x): 1600 equal light blocks
    fused_us_kernel<<<512 + NSB * BSZ, 256, SSC_SMEM>>>(
        ahip, wthip + WSZF, qhip, khip, wp, up, pvp, pip);

    // merge top-16, exact rescore, softmax, gather
    merge_rescore_gather<<<MROWS, 128>>>(pvp, pip, trp, S, wp, up, bvop, out);
}